// round 3
// baseline (speedup 1.0000x reference)
#include <cuda_runtime.h>

// Problem constants (fixed by the dataset shapes)
#define HB_ 32
#define WB_ 32
#define CC_ 64
#define HA_ 512
#define WA_ 512
#define NN_ 256
#define BB_ 4
#define PATCH_ (HB_ * WB_)   // 1024
#define PLANE_ (HA_ * WA_)   // 262144

// Select element k (0..3) of a float4 via SEL chain (ALU pipe is idle).
__device__ __forceinline__ float sel4(float4 q, int k) {
    float r = q.x;
    r = (k == 1) ? q.y : r;
    r = (k == 2) ? q.z : r;
    r = (k == 3) ? q.w : r;
    return r;
}

__global__ __launch_bounds__(256, 5)
void aerial_patch_sampler_kernel(const float* __restrict__ img,
                                 const float* __restrict__ pose,
                                 float* __restrict__ out)
{
    // Band folded into LOW bits so the 4 bands of one patch are co-scheduled
    // (fixes the round-2 L2 re-fetch thrash); bn remains b-major overall.
    const int bx   = blockIdx.x;
    const int bn   = bx >> 2;          // b * N + n
    const int band = bx & 3;           // 8-row band of the patch
    const int b    = bn >> 8;          // N = 256

    // Warp-tile remap: each warp covers an 8(wb) x 4(hb) patch tile.
    const int lane = threadIdx.x & 31;
    const int warp = threadIdx.x >> 5;                              // 0..7
    const int wb = (lane & 7) + ((warp & 3) << 3);                  // 0..31
    const int hb = (band << 3) + (lane >> 3) + ((warp >> 2) << 2);  // 0..31

    // Pose for this patch (broadcast)
    const float u  = __ldg(&pose[bn * 3 + 0]);
    const float v  = __ldg(&pose[bn * 3 + 1]);
    const float th = __ldg(&pose[bn * 3 + 2]);

    const float c = cosf(th);   // cos(-th) = cos(th)
    const float s = sinf(th);   // sin(-th) = -sin(th)

    const float gu0 = (float)(HB_ - 1 - hb);      // rows flipped
    const float gv0 = (float)(wb - WB_ / 2);      // centered on WB/2

    const float gu = u + c * gu0 + s * gv0;
    const float gv = v - s * gu0 + c * gv0;

    // Normalize exactly like the reference (FEATURE_SCALE = 1)
    const float gx = (gu + 0.5f) * (2.0f / (float)WA_) - 1.0f;
    const float gy = (gv + 0.5f) * (2.0f / (float)HA_) - 1.0f;
    const bool valid = (fabsf(gx) < 1.0f) && (fabsf(gy) < 1.0f);

    // Output: out[((bn)*C + cc)*1024 + hb*32 + wb]
    float* op = out + (size_t)bn * CC_ * PATCH_ + hb * WB_ + wb;

    if (!valid) {
        #pragma unroll
        for (int cc = 0; cc < CC_; cc++)
            op[cc * PATCH_] = 0.0f;
        return;
    }

    // Unnormalize (align_corners=False), same round-trip as reference
    const float ix = ((gx + 1.0f) * (float)WA_ - 1.0f) * 0.5f;
    const float iy = ((gy + 1.0f) * (float)HA_ - 1.0f) * 0.5f;

    const float x0f = floorf(ix);
    const float y0f = floorf(iy);
    const int x0 = (int)x0f;
    const int y0 = (int)y0f;
    const int x1 = x0 + 1;
    const int y1 = y0 + 1;

    const float wx1 = ix - x0f;
    const float wx0 = 1.0f - wx1;
    const float wy1 = iy - y0f;
    const float wy0 = 1.0f - wy1;

    const float* base = img + (size_t)b * CC_ * PLANE_;

    const bool interior = (x0 >= 0) && (x1 < WA_) && (y0 >= 0) && (y1 < HA_);

    if (interior) {
        // FAST PATH: one aligned float4 per row covers both x-taps when
        // (x0&3) < 3; predicated scalar fixup for the k==3 lanes.
        const int ab = x0 & ~3;          // 16B-aligned column base
        const int k  = x0 & 3;           // position of x0 inside the float4
        const bool need_fix = (k == 3);

        const float* r0 = base + y0 * WA_ + ab;   // row y0, channel 0
        const float* r1 = r0 + WA_;               // row y1 = y0+1
        const float* e0p = base + y0 * WA_ + x1;  // fixup addr row y0
        const float* e1p = e0p + WA_;             // fixup addr row y1

        #pragma unroll 1
        for (int cc0 = 0; cc0 < CC_; cc0 += 2) {
            const int offA = cc0 * PLANE_;
            const int offB = offA + PLANE_;
            // 4 independent 16B gathers in flight
            const float4 qa0 = __ldg((const float4*)(r0 + offA));
            const float4 qa1 = __ldg((const float4*)(r1 + offA));
            const float4 qb0 = __ldg((const float4*)(r0 + offB));
            const float4 qb1 = __ldg((const float4*)(r1 + offB));

            float ea0 = 0.f, ea1 = 0.f, eb0 = 0.f, eb1 = 0.f;
            if (need_fix) {              // ~25% of lanes, predicated
                ea0 = __ldg(e0p + offA);
                ea1 = __ldg(e1p + offA);
                eb0 = __ldg(e0p + offB);
                eb1 = __ldg(e1p + offB);
            }

            // channel cc0
            {
                const float f00 = sel4(qa0, k);
                const float f01 = sel4(qa1, k);
                const float f10 = need_fix ? ea0 : sel4(qa0, k + 1);
                const float f11 = need_fix ? ea1 : sel4(qa1, k + 1);
                const float h0 = wx0 * f00 + wx1 * f10;
                const float h1 = wx0 * f01 + wx1 * f11;
                op[cc0 * PATCH_] = wy0 * h0 + wy1 * h1;
            }
            // channel cc0+1
            {
                const float f00 = sel4(qb0, k);
                const float f01 = sel4(qb1, k);
                const float f10 = need_fix ? eb0 : sel4(qb0, k + 1);
                const float f11 = need_fix ? eb1 : sel4(qb1, k + 1);
                const float h0 = wx0 * f00 + wx1 * f10;
                const float h1 = wx0 * f01 + wx1 * f11;
                op[(cc0 + 1) * PATCH_] = wy0 * h0 + wy1 * h1;
            }
        }
        return;
    }

    // FALLBACK (edge samples): per-tap validity, scalar gathers.
    {
        const bool vx0 = (x0 >= 0) && (x0 < WA_);
        const bool vx1 = (x1 >= 0) && (x1 < WA_);
        const bool vy0 = (y0 >= 0) && (y0 < HA_);
        const bool vy1 = (y1 >= 0) && (y1 < HA_);

        const float w00 = (vx0 && vy0) ? (wx0 * wy0) : 0.0f;
        const float w10 = (vx1 && vy0) ? (wx1 * wy0) : 0.0f;
        const float w01 = (vx0 && vy1) ? (wx0 * wy1) : 0.0f;
        const float w11 = (vx1 && vy1) ? (wx1 * wy1) : 0.0f;

        const int xc0 = min(max(x0, 0), WA_ - 1);
        const int xc1 = min(max(x1, 0), WA_ - 1);
        const int yc0 = min(max(y0, 0), HA_ - 1);
        const int yc1 = min(max(y1, 0), HA_ - 1);

        const float* p00 = base + yc0 * WA_ + xc0;
        const float* p10 = base + yc0 * WA_ + xc1;
        const float* p01 = base + yc1 * WA_ + xc0;
        const float* p11 = base + yc1 * WA_ + xc1;

        #pragma unroll 1
        for (int cc0 = 0; cc0 < CC_; cc0 += 2) {
            float f00[2], f10[2], f01[2], f11[2];
            #pragma unroll
            for (int j = 0; j < 2; j++) {
                const int off = (cc0 + j) * PLANE_;
                f00[j] = __ldg(p00 + off);
                f10[j] = __ldg(p10 + off);
                f01[j] = __ldg(p01 + off);
                f11[j] = __ldg(p11 + off);
            }
            #pragma unroll
            for (int j = 0; j < 2; j++) {
                op[(cc0 + j) * PATCH_] =
                    w00 * f00[j] + w10 * f10[j] + w01 * f01[j] + w11 * f11[j];
            }
        }
    }
}

extern "C" void kernel_launch(void* const* d_in, const int* in_sizes, int n_in,
                              void* d_out, int out_size)
{
    const float* aer_feat = (const float*)d_in[0];   // (B, C, 512, 512) fp32
    const float* pose_uvr = (const float*)d_in[1];   // (B, N, 3) fp32
    float* out = (float*)d_out;                      // (B, N, C, 32, 32) fp32

    dim3 grid(BB_ * NN_ * 4);   // bn*4 + band: bands of a patch co-scheduled
    dim3 block(256);            // 8 warps, each an 8x4 pixel tile
    aerial_patch_sampler_kernel<<<grid, block>>>(aer_feat, pose_uvr, out);
}

// round 4
// speedup vs baseline: 1.7196x; 1.7196x over previous
#include <cuda_runtime.h>

// Problem constants (fixed by the dataset shapes)
#define HB_ 32
#define WB_ 32
#define CC_ 64
#define HA_ 512
#define WA_ 512
#define NN_ 256
#define BB_ 4
#define PATCH_ (HB_ * WB_)     // 1024
#define PLANE_ (HA_ * WA_)     // 262144

#define TW_ 48                 // max bbox width/height (31*sqrt2 + 4 margin < 48)
#define SPITCH_ 49             // odd pitch -> conflict-free LDS at 0 and 90 deg
#define TILE_WORDS_ (TW_ * SPITCH_)          // 2352
#define NSTAGE_ 8                             // channels staged per barrier pair
#define SMEM_BYTES_ (NSTAGE_ * TILE_WORDS_ * 4)  // 75264 B

extern __shared__ float s_tile[];  // [NSTAGE_][TILE_WORDS_]

__global__ __launch_bounds__(1024, 1)
void aerial_patch_sampler_kernel(const float* __restrict__ img,
                                 const float* __restrict__ pose,
                                 float* __restrict__ out)
{
    const int bn = blockIdx.x;        // b * N + n  (b-major: L2 batch locality)
    const int b  = bn >> 8;           // N = 256
    const int wb = threadIdx.x & 31;
    const int hb = threadIdx.x >> 5;

    // Pose (broadcast)
    const float u  = __ldg(&pose[bn * 3 + 0]);
    const float v  = __ldg(&pose[bn * 3 + 1]);
    const float th = __ldg(&pose[bn * 3 + 2]);
    const float c = cosf(th);   // cos(-th)
    const float s = sinf(th);   // -sin(-th)

    // ---- Image-space bounding box of this patch (ix = gu, iy = gv analytically).
    // gu = u + c*gu0 + s*gv0,  gv = v - s*gu0 + c*gv0; gu0 in [0,31], gv0 in [-16,15].
    const float ixmin = u + fminf(0.0f, 31.0f * c) + fminf(-16.0f * s, 15.0f * s);
    const float ixmax = u + fmaxf(0.0f, 31.0f * c) + fmaxf(-16.0f * s, 15.0f * s);
    const float iymin = v + fminf(0.0f, -31.0f * s) + fminf(-16.0f * c, 15.0f * c);
    const float iymax = v + fmaxf(0.0f, -31.0f * s) + fmaxf(-16.0f * c, 15.0f * c);

    // -1/+2 = (+1 for x1 tap) plus 1px fp-rounding margin each side
    int bx0 = (int)floorf(ixmin) - 1;
    int bx1 = (int)floorf(ixmax) + 2;
    int by0 = (int)floorf(iymin) - 1;
    int by1 = (int)floorf(iymax) + 2;
    bx0 = min(max(bx0, 0), WA_ - 1);
    by0 = min(max(by0, 0), HA_ - 1);
    bx1 = min(min(max(bx1, bx0), WA_ - 1), bx0 + TW_ - 1);
    by1 = min(min(max(by1, by0), HA_ - 1), by0 + TW_ - 1);
    const int w = bx1 - bx0 + 1;
    const int h = by1 - by0 + 1;
    const int npix = w * h;

    // ---- Per-pixel sample coords: exact fp32 round trip as the reference.
    const float gu0 = (float)(HB_ - 1 - hb);      // rows flipped
    const float gv0 = (float)(wb - WB_ / 2);      // centered on WB/2
    const float gu = u + c * gu0 + s * gv0;
    const float gv = v - s * gu0 + c * gv0;
    const float gx = (gu + 0.5f) * (2.0f / (float)WA_) - 1.0f;
    const float gy = (gv + 0.5f) * (2.0f / (float)HA_) - 1.0f;
    const bool valid = (fabsf(gx) < 1.0f) && (fabsf(gy) < 1.0f);
    const float ix = ((gx + 1.0f) * (float)WA_ - 1.0f) * 0.5f;
    const float iy = ((gy + 1.0f) * (float)HA_ - 1.0f) * 0.5f;

    const float x0f = floorf(ix);
    const float y0f = floorf(iy);
    const int x0 = (int)x0f;
    const int y0 = (int)y0f;
    const int x1 = x0 + 1;
    const int y1 = y0 + 1;

    const float wx1 = ix - x0f;
    const float wx0 = 1.0f - wx1;
    const float wy1 = iy - y0f;
    const float wy0 = 1.0f - wy1;

    const bool vx0 = valid && (x0 >= 0) && (x0 < WA_);
    const bool vx1 = valid && (x1 >= 0) && (x1 < WA_);
    const bool vy0 = valid && (y0 >= 0) && (y0 < HA_);
    const bool vy1 = valid && (y1 >= 0) && (y1 < HA_);

    const float w00 = (vx0 && vy0) ? (wx0 * wy0) : 0.0f;
    const float w10 = (vx1 && vy0) ? (wx1 * wy0) : 0.0f;
    const float w01 = (vx0 && vy1) ? (wx0 * wy1) : 0.0f;
    const float w11 = (vx1 && vy1) ? (wx1 * wy1) : 0.0f;

    // Tile-local tap indices. Clamp defensively: any tap with nonzero weight is
    // provably inside the bbox; zero-weight taps just need to stay in-tile.
    const int sx0 = min(max(x0 - bx0, 0), w - 1);
    const int sx1 = min(max(x1 - bx0, 0), w - 1);
    const int sy0 = min(max(y0 - by0, 0), h - 1);
    const int sy1 = min(max(y1 - by0, 0), h - 1);
    const int i00 = sy0 * SPITCH_ + sx0;
    const int i10 = sy0 * SPITCH_ + sx1;
    const int i01 = sy1 * SPITCH_ + sx0;
    const int i11 = sy1 * SPITCH_ + sx1;

    const float* base = img + (size_t)b * CC_ * PLANE_;
    float* op = out + (size_t)bn * CC_ * PATCH_ + threadIdx.x;  // coalesced per warp

    #pragma unroll 1
    for (int c0 = 0; c0 < CC_; c0 += NSTAGE_) {
        // ---- Stage NSTAGE_ channels of the bbox region into smem (coalesced).
        const float* gsrc = base + (size_t)c0 * PLANE_;
        for (int idx = threadIdx.x; idx < npix; idx += 1024) {
            const int ry = idx / w;
            const int rx = idx - ry * w;
            const float* g = gsrc + (by0 + ry) * WA_ + (bx0 + rx);
            const int sidx = ry * SPITCH_ + rx;
            #pragma unroll
            for (int j = 0; j < NSTAGE_; j++)            // 8 independent LDGs in flight
                s_tile[j * TILE_WORDS_ + sidx] = __ldg(g + j * PLANE_);
        }
        __syncthreads();

        // ---- Gather from smem (word-granular, scatter-insensitive) + store.
        #pragma unroll
        for (int j = 0; j < NSTAGE_; j++) {
            const float* t = s_tile + j * TILE_WORDS_;
            const float r = w00 * t[i00] + w10 * t[i10]
                          + w01 * t[i01] + w11 * t[i11];
            op[(c0 + j) * PATCH_] = r;
        }
        __syncthreads();   // tile reused next stage
    }
}

extern "C" void kernel_launch(void* const* d_in, const int* in_sizes, int n_in,
                              void* d_out, int out_size)
{
    const float* aer_feat = (const float*)d_in[0];   // (B, C, 512, 512) fp32
    const float* pose_uvr = (const float*)d_in[1];   // (B, N, 3) fp32
    float* out = (float*)d_out;                      // (B, N, C, 32, 32) fp32

    static int smem_set = 0;
    if (!smem_set) {
        cudaFuncSetAttribute(aerial_patch_sampler_kernel,
                             cudaFuncAttributeMaxDynamicSharedMemorySize,
                             SMEM_BYTES_);
        smem_set = 1;
    }

    dim3 grid(BB_ * NN_);   // one block per patch, b-major
    dim3 block(1024);       // thread = patch pixel (coalesced stores)
    aerial_patch_sampler_kernel<<<grid, block, SMEM_BYTES_>>>(aer_feat, pose_uvr, out);
}